// round 3
// baseline (speedup 1.0000x reference)
#include <cuda_runtime.h>
#include <cuda_bf16.h>

// LengthRegulator: out[b, t, :] = phoneme[b, tok(b,t), :]
// tok(b,t) = searchsorted_right(inclusive_cumsum(durations[b,:]), t), clip N-1.
// Shapes (fixed): B=16, N=256, D=512, T=2048. float32.

#define LR_B 16
#define LR_N 256
#define LR_D 512
#define LR_T 2048
#define FRAMES_PER_BLOCK 64
#define THREADS 256
#define VEC_PER_FRAME (LR_D / 4)   // 128 float4 per frame

__global__ __launch_bounds__(THREADS)
void length_regulator_kernel(const float4* __restrict__ phoneme4,
                             const int* __restrict__ durations,
                             float4* __restrict__ out4)
{
    const int b = blockIdx.y;
    const int frame_base = blockIdx.x * FRAMES_PER_BLOCK;
    const int tid = threadIdx.x;

    __shared__ int s_ends[LR_N];             // inclusive cumsum of durations[b,:]
    __shared__ int s_tok[FRAMES_PER_BLOCK];  // token index per frame

    // 1) single-warp shuffle scan: lane L owns durations[8L .. 8L+7]
    if (tid < 32) {
        const int lane = tid;
        const int4* drow = (const int4*)(durations + b * LR_N);
        int4 a = drow[lane * 2 + 0];
        int4 c = drow[lane * 2 + 1];
        int e[8];
        e[0] = a.x;
        e[1] = e[0] + a.y;
        e[2] = e[1] + a.z;
        e[3] = e[2] + a.w;
        e[4] = e[3] + c.x;
        e[5] = e[4] + c.y;
        e[6] = e[5] + c.z;
        e[7] = e[6] + c.w;
        int x = e[7];                         // lane total
        #pragma unroll
        for (int off = 1; off < 32; off <<= 1) {
            int y = __shfl_up_sync(0xffffffffu, x, off);
            if (lane >= off) x += y;
        }
        const int excl = x - e[7];            // exclusive prefix of lane totals
        #pragma unroll
        for (int j = 0; j < 8; ++j)
            s_ends[lane * 8 + j] = e[j] + excl;
    }
    __syncthreads();

    // 2) lower-bound search: first token n with ends[n] > t (9 steps for N=256)
    if (tid < FRAMES_PER_BLOCK) {
        const int t = frame_base + tid;
        int lo = 0, hi = LR_N;
        #pragma unroll
        for (int it = 0; it < 9; ++it) {
            if (lo < hi) {
                int mid = (lo + hi) >> 1;
                if (s_ends[mid] > t) hi = mid; else lo = mid + 1;
            }
        }
        s_tok[tid] = (lo < LR_N) ? lo : (LR_N - 1);
    }
    __syncthreads();

    // 3) copy: 64 frames * 128 float4 = 8192 float4 per block.
    //    4 batches of 8 independent gathers -> 8 stores (MLP = 8).
    const float4* __restrict__ ph_b  = phoneme4 + (size_t)b * LR_N * VEC_PER_FRAME;
    float4* __restrict__       out_b = out4 + ((size_t)b * LR_T + frame_base) * VEC_PER_FRAME;

    #pragma unroll
    for (int batch = 0; batch < 4; ++batch) {
        const int base = batch * 8 * THREADS + tid;
        float4 r[8];
        #pragma unroll
        for (int j = 0; j < 8; ++j) {
            const int i   = base + j * THREADS;
            const int f   = i >> 7;              // i / 128
            const int off = i & (VEC_PER_FRAME - 1);
            r[j] = ph_b[s_tok[f] * VEC_PER_FRAME + off];
        }
        #pragma unroll
        for (int j = 0; j < 8; ++j)
            out_b[base + j * THREADS] = r[j];
    }
}

extern "C" void kernel_launch(void* const* d_in, const int* in_sizes, int n_in,
                              void* d_out, int out_size)
{
    const float4* phoneme4  = (const float4*)d_in[0];   // (B, N, D) f32
    const int*    durations = (const int*)d_in[1];      // (B, N) i32
    float4*       out4      = (float4*)d_out;           // (B, T, D) f32

    dim3 grid(LR_T / FRAMES_PER_BLOCK, LR_B);  // (32, 16) = 512 blocks
    length_regulator_kernel<<<grid, THREADS>>>(phoneme4, durations, out4);
}

// round 4
// speedup vs baseline: 1.0934x; 1.0934x over previous
#include <cuda_runtime.h>
#include <cuda_bf16.h>

// LengthRegulator: out[b, t, :] = phoneme[b, tok(b,t), :]
// tok(b,t) = searchsorted_right(inclusive_cumsum(durations[b,:]), t), clip N-1.
// Shapes (fixed): B=16, N=256, D=512, T=2048. float32.

#define LR_B 16
#define LR_N 256
#define LR_D 512
#define LR_T 2048
#define FPB 16                      // frames per block
#define THREADS 128
#define VPF (LR_D / 4)              // 128 float4 per frame

__global__ __launch_bounds__(THREADS)
void length_regulator_kernel(const float4* __restrict__ phoneme4,
                             const int* __restrict__ durations,
                             float4* __restrict__ out4)
{
    const int b = blockIdx.y;
    const int frame_base = blockIdx.x * FPB;
    const int tid = threadIdx.x;

    __shared__ int s_ends[LR_N];
    __shared__ int s_tok[FPB];

    // Warp 0: shuffle scan of durations + binary search for this block's frames.
    if (tid < 32) {
        const int lane = tid;
        const int4* drow = (const int4*)(durations + b * LR_N);
        int4 a = drow[lane * 2 + 0];
        int4 c = drow[lane * 2 + 1];
        int e0 = a.x;
        int e1 = e0 + a.y;
        int e2 = e1 + a.z;
        int e3 = e2 + a.w;
        int e4 = e3 + c.x;
        int e5 = e4 + c.y;
        int e6 = e5 + c.z;
        int e7 = e6 + c.w;
        int x = e7;
        #pragma unroll
        for (int off = 1; off < 32; off <<= 1) {
            int y = __shfl_up_sync(0xffffffffu, x, off);
            if (lane >= off) x += y;
        }
        const int excl = x - e7;
        s_ends[lane * 8 + 0] = e0 + excl;
        s_ends[lane * 8 + 1] = e1 + excl;
        s_ends[lane * 8 + 2] = e2 + excl;
        s_ends[lane * 8 + 3] = e3 + excl;
        s_ends[lane * 8 + 4] = e4 + excl;
        s_ends[lane * 8 + 5] = e5 + excl;
        s_ends[lane * 8 + 6] = e6 + excl;
        s_ends[lane * 8 + 7] = e7 + excl;
        __syncwarp();

        if (lane < FPB) {
            const int t = frame_base + lane;
            int lo = 0, hi = LR_N;
            #pragma unroll
            for (int it = 0; it < 9; ++it) {
                if (lo < hi) {
                    int mid = (lo + hi) >> 1;
                    if (s_ends[mid] > t) hi = mid; else lo = mid + 1;
                }
            }
            s_tok[lane] = (lo < LR_N) ? lo : (LR_N - 1);
        }
    }
    __syncthreads();

    // Pull all 16 token indices into registers (4 x LDS.128).
    int tok[FPB];
    const int4* st4 = (const int4*)s_tok;
    #pragma unroll
    for (int q = 0; q < FPB / 4; ++q) {
        int4 v = st4[q];
        tok[q * 4 + 0] = v.x;
        tok[q * 4 + 1] = v.y;
        tok[q * 4 + 2] = v.z;
        tok[q * 4 + 3] = v.w;
    }

    // Copy: thread owns column `tid` of every frame. Warp lanes are
    // consecutive columns of the SAME frame -> 512B coalesced per gather.
    const float4* __restrict__ ph_b =
        phoneme4 + (size_t)b * LR_N * VPF + tid;
    float4* __restrict__ out_b =
        out4 + ((size_t)b * LR_T + frame_base) * VPF + tid;

    #pragma unroll
    for (int g = 0; g < FPB / 4; ++g) {
        float4 r0 = ph_b[tok[g * 4 + 0] * VPF];
        float4 r1 = ph_b[tok[g * 4 + 1] * VPF];
        float4 r2 = ph_b[tok[g * 4 + 2] * VPF];
        float4 r3 = ph_b[tok[g * 4 + 3] * VPF];
        out_b[(g * 4 + 0) * VPF] = r0;
        out_b[(g * 4 + 1) * VPF] = r1;
        out_b[(g * 4 + 2) * VPF] = r2;
        out_b[(g * 4 + 3) * VPF] = r3;
    }
}

extern "C" void kernel_launch(void* const* d_in, const int* in_sizes, int n_in,
                              void* d_out, int out_size)
{
    const float4* phoneme4  = (const float4*)d_in[0];   // (B, N, D) f32
    const int*    durations = (const int*)d_in[1];      // (B, N) i32
    float4*       out4      = (float4*)d_out;           // (B, T, D) f32

    dim3 grid(LR_T / FPB, LR_B);    // (128, 16) = 2048 blocks
    length_regulator_kernel<<<grid, THREADS>>>(phoneme4, durations, out4);
}